// round 12
// baseline (speedup 1.0000x reference)
#include <cuda_runtime.h>
#include <cuda_fp16.h>

#define Bn 4096
#define Sn 64
#define Un 128
#define Mn 32
#define NUNF 6
#define EPSF 1e-8f
#define NPAIR 7
#define NWARP (2*NPAIR)
#define NTHR (NWARP*32)

__device__ __forceinline__ float ftanh(float x) {
    float t; asm("tanh.approx.f32 %0, %1;" : "=f"(t) : "f"(x));
    return t;
}
__device__ __forceinline__ void barpair(int pid) {
    asm volatile("bar.sync %0, 64;" :: "r"(pid + 1) : "memory");
}
__device__ __forceinline__ float aclr(float a, int& idx) {
    unsigned ai = __float_as_uint(a);
    idx = (int)(ai & 0x7Fu);
    return __uint_as_float(ai & 0xFFFFFF80u);
}
__device__ __forceinline__ unsigned packh2(float a, float b) {
    __half2 h = __floats2half2_rn(a, b);
    return *(unsigned*)&h;
}
__device__ __forceinline__ __half2 u2h(unsigned u) { return *(__half2*)&u; }

// math step: V01/V23 are float2 (batches 0,1 / 2,3)
#define MATHH(AF,V01,V23,BJ,WJ,F) { \
    float wa = fabsf(WJ); float t; \
    t = ftanh(fmaf(AF, V01.x, BJ)); mN0.F = fmaf(t,WJ,mN0.F); mD0.F = fmaf(t,wa,mD0.F); \
    t = ftanh(fmaf(AF, V01.y, BJ)); mN1.F = fmaf(t,WJ,mN1.F); mD1.F = fmaf(t,wa,mD1.F); \
    t = ftanh(fmaf(AF, V23.x, BJ)); mN2.F = fmaf(t,WJ,mN2.F); mD2.F = fmaf(t,wa,mD2.F); \
    t = ftanh(fmaf(AF, V23.y, BJ)); mN3.F = fmaf(t,WJ,mN3.F); mD3.F = fmaf(t,wa,mD3.F); }

// Fused LTC kernel. 148 CTAs x 448 threads (7 warp pairs, 4 batches/pair).
// Per-dst compacted synapses; src idx embedded in low 7 mantissa bits of fp32 'a';
// b and w packed as half2 in one uint4 plane (8 wf/entry weights vs 12);
// v broadcast stored as half4 (uint2) -> 8-byte gathers. All math fp32.
__global__ __launch_bounds__(NTHR, 1) void ltc_all(
    const float* __restrict__ inputs, const float* __restrict__ state,
    const float* __restrict__ gleak,  const float* __restrict__ vleak,
    const float* __restrict__ cm,
    const float* __restrict__ sigma,  const float* __restrict__ mu,
    const float* __restrict__ w,      const float* __restrict__ erev,
    const float* __restrict__ ssig,   const float* __restrict__ smu,
    const float* __restrict__ sw,     const float* __restrict__ serev,
    const float* __restrict__ mask,   const float* __restrict__ smask,
    const float* __restrict__ inw,    const float* __restrict__ inb,
    const float* __restrict__ outw,   const float* __restrict__ outb,
    float* __restrict__ dout)
{
    extern __shared__ float sm[];
    float*    sAf  = sm;                     // Un*Un: a fp32 (compacted, idx-embedded)
    uint4*    sBW  = (uint4*)(sm + Un*Un);   // Un*32 uint4: {b01,b23,w01,w23} half2
    unsigned short* sBW16 = (unsigned short*)sBW;
    float*    sVq  = sm + 2*Un*Un;           // NPAIR*512: v as half4 (uint2) per src
    float*    sXc  = sVq + NPAIR*512;        // NPAIR*512: xq staging / exchange
    float*    sNB  = sXc + NPAIR*512;        // Un nbase
    float*    sDB  = sNB + Un;               // Un dbase
    int*      sL   = (int*)(sDB + Un);       // [0]=recurrent L, [1]=sensory Ls

    int tid = threadIdx.x;
    if (tid == 0) { sL[0] = 0; sL[1] = 0; }

    // ---- A1: fold sensory params into SMEM (dense, b/w packed) ----
    {
        const float4* s4 = (const float4*)ssig;
        const float4* m4 = (const float4*)smu;
        const float4* w4 = (const float4*)sw;
        const float4* e4 = (const float4*)serev;
        const float4* k4 = (const float4*)smask;
        for (int i = tid; i < Sn*Un/4; i += NTHR) {   // i = s*32 + lane
            float4 sg = s4[i], mm = m4[i], ww = w4[i], ee = e4[i], kk = k4[i];
            float4 a;
            a.x = 0.5f*sg.x; a.y = 0.5f*sg.y; a.z = 0.5f*sg.z; a.w = 0.5f*sg.w;
            float b0 = -a.x*mm.x, b1 = -a.y*mm.y, b2 = -a.z*mm.z, b3 = -a.w*mm.w;
            float w0 = 0.5f*ww.x*kk.x*ee.x, w1 = 0.5f*ww.y*kk.y*ee.y;
            float w2 = 0.5f*ww.z*kk.z*ee.z, w3 = 0.5f*ww.w*kk.w*ee.w;
            ((float4*)sAf)[i] = a;
            uint4 bw;
            bw.x = packh2(b0, b1); bw.y = packh2(b2, b3);
            bw.z = packh2(w0, w1); bw.w = packh2(w2, w3);
            sBW[i] = bw;
        }
    }
    __syncthreads();

    int warp = tid >> 5, lane = tid & 31, d0 = lane * 4;
    int pid = warp % NPAIR;
    bool hi = (warp >= NPAIR);
    int start = (int)(((long long)blockIdx.x       * Bn) / gridDim.x);
    int end   = (int)(((long long)(blockIdx.x + 1) * Bn) / gridDim.x);
    int b0 = start + pid*4;
    int b1 = (b0+1 < end) ? b0+1 : end-1;
    int b2 = (b0+2 < end) ? b0+2 : end-1;
    int b3 = (b0+3 < end) ? b0+3 : end-1;
    unsigned* vqh = (unsigned*)(sVq + pid*512);   // 128 x uint2 (half4) per pair
    float* xch = sXc + pid*512;                   // xq (64 float4) then exchange buffer

    float colSn = 0.f, colSd = 0.f;
    int cnt_s = 0;
    int myl = tid >> 2, myj = tid & 3;            // for tid<128: lane/comp of column

    // ---- scan 1 (tid<128): sensory col-sums + in-place compaction ----
    if (tid < Un) {
        for (int s = 0; s < Sn; ++s) {
            int base16 = (s*32 + myl)*8;
            unsigned short hb = sBW16[base16 + myj];
            unsigned short hw = sBW16[base16 + 4 + myj];
            float wf = __half2float(*(__half*)&hw);
            colSn += wf; colSd += fabsf(wf);
            if (hw != 0) {
                unsigned ai = __float_as_uint(sAf[s*Un + tid]);
                int wb = (cnt_s*32 + myl)*8;
                sAf[cnt_s*Un + tid] = __uint_as_float((ai & 0xFFFFFF80u) | (unsigned)s);
                sBW16[wb + myj] = hb;
                sBW16[wb + 4 + myj] = hw;
                cnt_s++;
            }
        }
        atomicMax(&sL[1], cnt_s);
    }
    // ---- HIGH warps stage xq[s] = (x_b0, x_b1, x_b2, x_b3) ----
    if (hi) {
        for (int s = lane; s < Sn; s += 32) {
            float iw_ = inw[s], ib_ = inb[s];
            float4 xv;
            xv.x = fmaf(inputs[b0*Sn + s], iw_, ib_);
            xv.y = fmaf(inputs[b1*Sn + s], iw_, ib_);
            xv.z = fmaf(inputs[b2*Sn + s], iw_, ib_);
            xv.w = fmaf(inputs[b3*Sn + s], iw_, ib_);
            ((float4*)xch)[s] = xv;
        }
    }
    __syncthreads();
    int Ls = sL[1];
    if (tid < Un) {   // pad sensory rows (w=0 -> exact zero contribution)
        for (int e = cnt_s; e < Ls; ++e) {
            int wb = (e*32 + myl)*8;
            sAf[e*Un + tid] = 0.f;
            sBW16[wb + myj] = 0; sBW16[wb + 4 + myj] = 0;
        }
    }
    __syncthreads();

    // ---- sensory gather loop (compacted, pair-split) ----
    float4 mN0 = make_float4(0,0,0,0), mN1 = mN0, mN2 = mN0, mN3 = mN0;
    float4 mD0 = mN0, mD1 = mN0, mD2 = mN0, mD3 = mN0;
    {
        const float4* A4 = (const float4*)sAf;
        const float4* xq4 = (const float4*)xch;
        int Lsh  = (Ls + 1) >> 1;
        int eB = hi ? Lsh : 0;
        int eE = hi ? Ls  : Lsh;
        for (int e = eB; e < eE; ++e) {
            float4 a  = A4[e*32 + lane];
            uint4 bw  = sBW[e*32 + lane];
            float2 bxy = __half22float2(u2h(bw.x)), bzw = __half22float2(u2h(bw.y));
            float2 wxy = __half22float2(u2h(bw.z)), wzw = __half22float2(u2h(bw.w));
            int ix, iy, iz, iw_;
            float ax = aclr(a.x, ix), ay = aclr(a.y, iy);
            float az = aclr(a.z, iz), aw = aclr(a.w, iw_);
            float4 g0 = xq4[ix], g1 = xq4[iy], g2 = xq4[iz], g3 = xq4[iw_];
            float2 g0a = make_float2(g0.x, g0.y), g0b = make_float2(g0.z, g0.w);
            float2 g1a = make_float2(g1.x, g1.y), g1b = make_float2(g1.z, g1.w);
            float2 g2a = make_float2(g2.x, g2.y), g2b = make_float2(g2.z, g2.w);
            float2 g3a = make_float2(g3.x, g3.y), g3b = make_float2(g3.z, g3.w);
            MATHH(ax, g0a, g0b, bxy.x, wxy.x, x)
            MATHH(ay, g1a, g1b, bxy.y, wxy.y, y)
            MATHH(az, g2a, g2b, bzw.x, wzw.x, z)
            MATHH(aw, g3a, g3b, bzw.y, wzw.y, w)
        }
    }
    float4 aN0 = mN0, aN1 = mN1, aN2 = mN2, aN3 = mN3;
    float4 aD0 = mD0, aD1 = mD1, aD2 = mD2, aD3 = mD3;
    __syncthreads();   // done reading sensory planes + xq

    // ---- A2: fold recurrent params into SMEM (dense, overwrite) ----
    {
        const float4* s4 = (const float4*)sigma;
        const float4* m4 = (const float4*)mu;
        const float4* w4 = (const float4*)w;
        const float4* e4 = (const float4*)erev;
        const float4* k4 = (const float4*)mask;
        for (int i = tid; i < Un*Un/4; i += NTHR) {
            float4 sg = s4[i], mm = m4[i], ww = w4[i], ee = e4[i], kk = k4[i];
            float4 a;
            a.x = 0.5f*sg.x; a.y = 0.5f*sg.y; a.z = 0.5f*sg.z; a.w = 0.5f*sg.w;
            float b0f = -a.x*mm.x, b1f = -a.y*mm.y, b2f = -a.z*mm.z, b3f = -a.w*mm.w;
            float w0f = 0.5f*ww.x*kk.x*ee.x, w1f = 0.5f*ww.y*kk.y*ee.y;
            float w2f = 0.5f*ww.z*kk.z*ee.z, w3f = 0.5f*ww.w*kk.w*ee.w;
            ((float4*)sAf)[i] = a;
            uint4 bw;
            bw.x = packh2(b0f, b1f); bw.y = packh2(b2f, b3f);
            bw.z = packh2(w0f, w1f); bw.w = packh2(w2f, w3f);
            sBW[i] = bw;
        }
    }
    __syncthreads();

    // ---- scan 2 (tid<128): recurrent col-sums + compaction + base assembly ----
    int cnt = 0;
    if (tid < Un) {
        float n = colSn, d = colSd;
        for (int s = 0; s < Un; ++s) {
            int base16 = (s*32 + myl)*8;
            unsigned short hb = sBW16[base16 + myj];
            unsigned short hw = sBW16[base16 + 4 + myj];
            float wf = __half2float(*(__half*)&hw);
            n += wf; d += fabsf(wf);
            if (hw != 0) {
                unsigned ai = __float_as_uint(sAf[s*Un + tid]);
                int wb = (cnt*32 + myl)*8;
                sAf[cnt*Un + tid] = __uint_as_float((ai & 0xFFFFFF80u) | (unsigned)s);
                sBW16[wb + myj] = hb;
                sBW16[wb + 4 + myj] = hw;
                cnt++;
            }
        }
        atomicMax(&sL[0], cnt);
        float gl = gleak[tid];
        sNB[tid] = fmaf(gl, vleak[tid], n);
        sDB[tid] = cm[tid]*(float)NUNF + gl + EPSF + d;
    }
    __syncthreads();
    int L = sL[0];
    if (tid < Un) {
        for (int e = cnt; e < L; ++e) {
            int wb = (e*32 + myl)*8;
            sAf[e*Un + tid] = 0.f;
            sBW16[wb + myj] = 0; sBW16[wb + 4 + myj] = 0;
        }
    }
    __syncthreads();

    // ---- init constants; bases folded only into LOW warp's partials ----
    float4 cmt;
    {
        float4 cm4 = *(const float4*)(cm + d0);
        cmt.x = cm4.x*(float)NUNF; cmt.y = cm4.y*(float)NUNF;
        cmt.z = cm4.z*(float)NUNF; cmt.w = cm4.w*(float)NUNF;
        if (!hi) {
            float4 nb4 = *(const float4*)(sNB + d0);
            float4 db4 = *(const float4*)(sDB + d0);
            #define ADD4(T,S) T.x += S.x; T.y += S.y; T.z += S.z; T.w += S.w;
            ADD4(aN0, nb4) ADD4(aN1, nb4) ADD4(aN2, nb4) ADD4(aN3, nb4)
            ADD4(aD0, db4) ADD4(aD1, db4) ADD4(aD2, db4) ADD4(aD3, db4)
            #undef ADD4
        }
    }

    const float4* sA = (const float4*)sAf;

    // v init: vqh[s] = half4 (v_b0,v_b1,v_b2,v_b3); LOW writes word0, HIGH word1
    float4 vA, vB;
    {
        int ba = hi ? b2 : b0, bb = hi ? b3 : b1;
        vA = *(const float4*)(state + ba*Un + d0);
        vB = *(const float4*)(state + bb*Un + d0);
        int off = hi ? 1 : 0;
        vqh[2*(d0+0) + off] = packh2(vA.x, vB.x);
        vqh[2*(d0+1) + off] = packh2(vA.y, vB.y);
        vqh[2*(d0+2) + off] = packh2(vA.z, vB.z);
        vqh[2*(d0+3) + off] = packh2(vA.w, vB.w);
    }
    barpair(pid);

    int Lh   = (L + 1) >> 1;
    int eBeg = hi ? Lh : 0;
    int eEnd = hi ? L  : Lh;
    float4* x4 = (float4*)xch;
    const uint2* vq2 = (const uint2*)vqh;

    for (int it = 0; it < NUNF; ++it) {
        mN0 = aN0; mN1 = aN1; mN2 = aN2; mN3 = aN3;
        mD0 = aD0; mD1 = aD1; mD2 = aD2; mD3 = aD3;

        #pragma unroll 2
        for (int e = eBeg; e < eEnd; ++e) {
            float4 a  = sA[e*32 + lane];
            uint4 bw  = sBW[e*32 + lane];
            float2 bxy = __half22float2(u2h(bw.x)), bzw = __half22float2(u2h(bw.y));
            float2 wxy = __half22float2(u2h(bw.z)), wzw = __half22float2(u2h(bw.w));
            int ix, iy, iz, iw_;
            float ax = aclr(a.x, ix), ay = aclr(a.y, iy);
            float az = aclr(a.z, iz), aw = aclr(a.w, iw_);
            uint2 gx = vq2[ix], gy = vq2[iy], gz = vq2[iz], gw = vq2[iw_];
            float2 vx01 = __half22float2(u2h(gx.x)), vx23 = __half22float2(u2h(gx.y));
            float2 vy01 = __half22float2(u2h(gy.x)), vy23 = __half22float2(u2h(gy.y));
            float2 vz01 = __half22float2(u2h(gz.x)), vz23 = __half22float2(u2h(gz.y));
            float2 vw01 = __half22float2(u2h(gw.x)), vw23 = __half22float2(u2h(gw.y));
            MATHH(ax, vx01, vx23, bxy.x, wxy.x, x)
            MATHH(ay, vy01, vy23, bxy.y, wxy.y, y)
            MATHH(az, vz01, vz23, bzw.x, wzw.x, z)
            MATHH(aw, vw01, vw23, bzw.y, wzw.y, w)
        }

        // ---- pairwise exchange & update (fp32) ----
        float4 vnA, vnB;
        if (hi) {
            x4[lane]      = mN0;  x4[32 + lane] = mD0;
            x4[64 + lane] = mN1;  x4[96 + lane] = mD1;
        }
        barpair(pid);
        if (!hi) {
            float4 pn0 = x4[lane],      pd0 = x4[32 + lane];
            float4 pn1 = x4[64 + lane], pd1 = x4[96 + lane];
            vnA.x = __fdividef(fmaf(cmt.x, vA.x, mN0.x + pn0.x), mD0.x + pd0.x);
            vnA.y = __fdividef(fmaf(cmt.y, vA.y, mN0.y + pn0.y), mD0.y + pd0.y);
            vnA.z = __fdividef(fmaf(cmt.z, vA.z, mN0.z + pn0.z), mD0.z + pd0.z);
            vnA.w = __fdividef(fmaf(cmt.w, vA.w, mN0.w + pn0.w), mD0.w + pd0.w);
            vnB.x = __fdividef(fmaf(cmt.x, vB.x, mN1.x + pn1.x), mD1.x + pd1.x);
            vnB.y = __fdividef(fmaf(cmt.y, vB.y, mN1.y + pn1.y), mD1.y + pd1.y);
            vnB.z = __fdividef(fmaf(cmt.z, vB.z, mN1.z + pn1.z), mD1.z + pd1.z);
            vnB.w = __fdividef(fmaf(cmt.w, vB.w, mN1.w + pn1.w), mD1.w + pd1.w);
            x4[lane]      = mN2;  x4[32 + lane] = mD2;
            x4[64 + lane] = mN3;  x4[96 + lane] = mD3;
        }
        barpair(pid);
        if (hi) {
            float4 pn2 = x4[lane],      pd2 = x4[32 + lane];
            float4 pn3 = x4[64 + lane], pd3 = x4[96 + lane];
            vnA.x = __fdividef(fmaf(cmt.x, vA.x, mN2.x + pn2.x), mD2.x + pd2.x);
            vnA.y = __fdividef(fmaf(cmt.y, vA.y, mN2.y + pn2.y), mD2.y + pd2.y);
            vnA.z = __fdividef(fmaf(cmt.z, vA.z, mN2.z + pn2.z), mD2.z + pd2.z);
            vnA.w = __fdividef(fmaf(cmt.w, vA.w, mN2.w + pn2.w), mD2.w + pd2.w);
            vnB.x = __fdividef(fmaf(cmt.x, vB.x, mN3.x + pn3.x), mD3.x + pd3.x);
            vnB.y = __fdividef(fmaf(cmt.y, vB.y, mN3.y + pn3.y), mD3.y + pd3.y);
            vnB.z = __fdividef(fmaf(cmt.z, vB.z, mN3.z + pn3.z), mD3.z + pd3.z);
            vnB.w = __fdividef(fmaf(cmt.w, vB.w, mN3.w + pn3.w), mD3.w + pd3.w);
        }
        {   // publish new v halves as fp16 pairs
            int off = hi ? 1 : 0;
            vqh[2*(d0+0) + off] = packh2(vnA.x, vnB.x);
            vqh[2*(d0+1) + off] = packh2(vnA.y, vnB.y);
            vqh[2*(d0+2) + off] = packh2(vnA.z, vnB.z);
            vqh[2*(d0+3) + off] = packh2(vnA.w, vnB.w);
        }
        vA = vnA; vB = vnB;
        barpair(pid);
    }

    // ---- outputs (full fp32 v) ----
    int ba = hi ? b2 : b0, bb = hi ? b3 : b1;
    ((float4*)(dout + Bn*Mn + ba*Un))[lane] = vA;
    ((float4*)(dout + Bn*Mn + bb*Un))[lane] = vB;
    if (d0 < Mn) {
        float4 ow = *(const float4*)(outw + d0);
        float4 ob = *(const float4*)(outb + d0);
        float4 o;
        o.x = fmaf(vA.x, ow.x, ob.x); o.y = fmaf(vA.y, ow.y, ob.y);
        o.z = fmaf(vA.z, ow.z, ob.z); o.w = fmaf(vA.w, ow.w, ob.w);
        ((float4*)(dout + ba*Mn))[lane] = o;
        o.x = fmaf(vB.x, ow.x, ob.x); o.y = fmaf(vB.y, ow.y, ob.y);
        o.z = fmaf(vB.z, ow.z, ob.z); o.w = fmaf(vB.w, ow.w, ob.w);
        ((float4*)(dout + bb*Mn))[lane] = o;
    }
}

extern "C" void kernel_launch(void* const* d_in, const int* in_sizes, int n_in,
                              void* d_out, int out_size) {
    const float* inputs = (const float*)d_in[0];
    const float* state  = (const float*)d_in[1];
    const float* gleak  = (const float*)d_in[2];
    const float* vleak  = (const float*)d_in[3];
    const float* cm     = (const float*)d_in[4];
    const float* sigma  = (const float*)d_in[5];
    const float* mu     = (const float*)d_in[6];
    const float* w      = (const float*)d_in[7];
    const float* erev   = (const float*)d_in[8];
    const float* ssig   = (const float*)d_in[9];
    const float* smu    = (const float*)d_in[10];
    const float* sw     = (const float*)d_in[11];
    const float* serev  = (const float*)d_in[12];
    const float* mask   = (const float*)d_in[13];
    const float* smask  = (const float*)d_in[14];
    const float* inw    = (const float*)d_in[15];
    const float* inb    = (const float*)d_in[16];
    const float* outw   = (const float*)d_in[17];
    const float* outb   = (const float*)d_in[18];
    float* out = (float*)d_out;

    // sAf 64KB + sBW 64KB + vq/xch 28KB + bases ~1KB  => ~157KB
    size_t shmem = (size_t)(2*Un*Un + NPAIR*512*2 + 2*Un + 2) * sizeof(float);
    cudaFuncSetAttribute(ltc_all, cudaFuncAttributeMaxDynamicSharedMemorySize, (int)shmem);
    ltc_all<<<148, NTHR, shmem>>>(inputs, state, gleak, vleak, cm,
                                  sigma, mu, w, erev, ssig, smu, sw, serev,
                                  mask, smask, inw, inb, outw, outb, out);
}

// round 13
// speedup vs baseline: 1.2620x; 1.2620x over previous
#include <cuda_runtime.h>
#include <cuda_fp16.h>

#define Bn 4096
#define Sn 64
#define Un 128
#define Mn 32
#define NUNF 6
#define EPSF 1e-8f
#define NPAIR 7
#define NWARP (2*NPAIR)
#define NTHR (NWARP*32)

__device__ __forceinline__ float ftanh(float x) {
    float t; asm("tanh.approx.f32 %0, %1;" : "=f"(t) : "f"(x));
    return t;
}
__device__ __forceinline__ void barpair(int pid) {
    asm volatile("bar.sync %0, 64;" :: "r"(pid + 1) : "memory");
}
// extract embedded src index; 'a' is used UNSTRIPPED as coefficient
// (low-7-bit mantissa perturbation <= 2^-16 relative — below fp16-v noise)
__device__ __forceinline__ int aidx(float a) {
    return (int)(__float_as_uint(a) & 0x7Fu);
}
__device__ __forceinline__ unsigned packh2(float a, float b) {
    __half2 h = __floats2half2_rn(a, b);
    return *(unsigned*)&h;
}

// math step for fp32 gathered float4 (sensory path)
#define MATH4(AF,GV,BJ,WJ,F) { \
    float wa = fabsf(WJ); float t; \
    t = ftanh(fmaf(AF, GV.x, BJ)); mN0.F = fmaf(t,WJ,mN0.F); mD0.F = fmaf(t,wa,mD0.F); \
    t = ftanh(fmaf(AF, GV.y, BJ)); mN1.F = fmaf(t,WJ,mN1.F); mD1.F = fmaf(t,wa,mD1.F); \
    t = ftanh(fmaf(AF, GV.z, BJ)); mN2.F = fmaf(t,WJ,mN2.F); mD2.F = fmaf(t,wa,mD2.F); \
    t = ftanh(fmaf(AF, GV.w, BJ)); mN3.F = fmaf(t,WJ,mN3.F); mD3.F = fmaf(t,wa,mD3.F); }

// math step for fp16-packed v gather: V01/V23 are float2 (batches 0,1 / 2,3)
#define MATHH(AF,V01,V23,BJ,WJ,F) { \
    float wa = fabsf(WJ); float t; \
    t = ftanh(fmaf(AF, V01.x, BJ)); mN0.F = fmaf(t,WJ,mN0.F); mD0.F = fmaf(t,wa,mD0.F); \
    t = ftanh(fmaf(AF, V01.y, BJ)); mN1.F = fmaf(t,WJ,mN1.F); mD1.F = fmaf(t,wa,mD1.F); \
    t = ftanh(fmaf(AF, V23.x, BJ)); mN2.F = fmaf(t,WJ,mN2.F); mD2.F = fmaf(t,wa,mD2.F); \
    t = ftanh(fmaf(AF, V23.y, BJ)); mN3.F = fmaf(t,WJ,mN3.F); mD3.F = fmaf(t,wa,mD3.F); }

// Fused LTC kernel. 148 CTAs x 448 threads (7 warp pairs, 4 batches/pair).
// Sensory + recurrent synapses per-dst compacted (50% masks), src idx embedded
// in low 7 mantissa bits of 'a' (used unstripped). Weights fp32; v broadcast
// stored as half4 (uint2) -> 8-byte gathers. All math fp32.
__global__ __launch_bounds__(NTHR, 1) void ltc_all(
    const float* __restrict__ inputs, const float* __restrict__ state,
    const float* __restrict__ gleak,  const float* __restrict__ vleak,
    const float* __restrict__ cm,
    const float* __restrict__ sigma,  const float* __restrict__ mu,
    const float* __restrict__ w,      const float* __restrict__ erev,
    const float* __restrict__ ssig,   const float* __restrict__ smu,
    const float* __restrict__ sw,     const float* __restrict__ serev,
    const float* __restrict__ mask,   const float* __restrict__ smask,
    const float* __restrict__ inw,    const float* __restrict__ inb,
    const float* __restrict__ outw,   const float* __restrict__ outb,
    float* __restrict__ dout)
{
    extern __shared__ float sm[];
    float* sAf = sm;                         // Un*Un plane: a (compacted, idx-embedded)
    float* sBf = sm + Un*Un;                 // Un*Un plane: b
    float* sWf = sm + 2*Un*Un;               // Un*Un plane: we
    float* sVq = sm + 3*Un*Un;               // NPAIR*512: v as half4 (uint2) per src
    float* sXc = sVq + NPAIR*512;            // NPAIR*512: xq staging / exchange
    float* sNB = sXc + NPAIR*512;            // Un nbase
    float* sDB = sNB + Un;                   // Un dbase
    int*   sL  = (int*)(sDB + Un);           // [0]=recurrent L, [1]=sensory Ls

    int tid = threadIdx.x;
    if (tid == 0) { sL[0] = 0; sL[1] = 0; }

    // ---- A1: fold sensory params into SMEM (dense) ----
    {
        const float4* s4 = (const float4*)ssig;
        const float4* m4 = (const float4*)smu;
        const float4* w4 = (const float4*)sw;
        const float4* e4 = (const float4*)serev;
        const float4* k4 = (const float4*)smask;
        for (int i = tid; i < Sn*Un/4; i += NTHR) {
            float4 sg = s4[i], mm = m4[i], ww = w4[i], ee = e4[i], kk = k4[i];
            float4 a, b, we;
            a.x = 0.5f*sg.x; a.y = 0.5f*sg.y; a.z = 0.5f*sg.z; a.w = 0.5f*sg.w;
            b.x = -a.x*mm.x; b.y = -a.y*mm.y; b.z = -a.z*mm.z; b.w = -a.w*mm.w;
            we.x = 0.5f*ww.x*kk.x*ee.x; we.y = 0.5f*ww.y*kk.y*ee.y;
            we.z = 0.5f*ww.z*kk.z*ee.z; we.w = 0.5f*ww.w*kk.w*ee.w;
            ((float4*)sAf)[i] = a; ((float4*)sBf)[i] = b; ((float4*)sWf)[i] = we;
        }
    }
    __syncthreads();

    int warp = tid >> 5, lane = tid & 31, d0 = lane * 4;
    int pid = warp % NPAIR;
    bool hi = (warp >= NPAIR);
    int start = (int)(((long long)blockIdx.x       * Bn) / gridDim.x);
    int end   = (int)(((long long)(blockIdx.x + 1) * Bn) / gridDim.x);
    int b0 = start + pid*4;
    int b1 = (b0+1 < end) ? b0+1 : end-1;
    int b2 = (b0+2 < end) ? b0+2 : end-1;
    int b3 = (b0+3 < end) ? b0+3 : end-1;
    unsigned* vqh = (unsigned*)(sVq + pid*512);   // 128 x uint2 (half4) per pair
    float* xch = sXc + pid*512;                   // xq (64 float4) then exchange buffer

    float colSn = 0.f, colSd = 0.f;
    int cnt_s = 0;

    // ---- scan 1 (tid<128): sensory col-sums + in-place compaction ----
    if (tid < Un) {
        for (int s = 0; s < Sn; ++s) {
            float wv = sWf[s*Un + tid];
            colSn += wv; colSd += fabsf(wv);
            if (wv != 0.f) {
                unsigned ai = __float_as_uint(sAf[s*Un + tid]);
                float bv = sBf[s*Un + tid];
                sAf[cnt_s*Un + tid] = __uint_as_float((ai & 0xFFFFFF80u) | (unsigned)s);
                sBf[cnt_s*Un + tid] = bv;
                sWf[cnt_s*Un + tid] = wv;
                cnt_s++;
            }
        }
        atomicMax(&sL[1], cnt_s);
    }
    // ---- HIGH warps stage xq[s] = (x_b0, x_b1, x_b2, x_b3) ----
    if (hi) {
        for (int s = lane; s < Sn; s += 32) {
            float iw_ = inw[s], ib_ = inb[s];
            float4 xv;
            xv.x = fmaf(inputs[b0*Sn + s], iw_, ib_);
            xv.y = fmaf(inputs[b1*Sn + s], iw_, ib_);
            xv.z = fmaf(inputs[b2*Sn + s], iw_, ib_);
            xv.w = fmaf(inputs[b3*Sn + s], iw_, ib_);
            ((float4*)xch)[s] = xv;
        }
    }
    __syncthreads();
    int Ls = sL[1];
    if (tid < Un) {   // pad sensory rows (w=0 -> exact zero contribution)
        for (int e = cnt_s; e < Ls; ++e) {
            sAf[e*Un + tid] = 0.f; sBf[e*Un + tid] = 0.f; sWf[e*Un + tid] = 0.f;
        }
    }
    __syncthreads();

    // ---- sensory gather loop (compacted, pair-split, fp32 gathers) ----
    float4 mN0 = make_float4(0,0,0,0), mN1 = mN0, mN2 = mN0, mN3 = mN0;
    float4 mD0 = mN0, mD1 = mN0, mD2 = mN0, mD3 = mN0;
    {
        const float4* A4 = (const float4*)sAf;
        const float4* B4 = (const float4*)sBf;
        const float4* W4 = (const float4*)sWf;
        const float4* xq4 = (const float4*)xch;
        int Lsh  = (Ls + 1) >> 1;
        int eB = hi ? Lsh : 0;
        int eE = hi ? Ls  : Lsh;
        for (int e = eB; e < eE; ++e) {
            float4 a  = A4[e*32 + lane];
            float4 bb = B4[e*32 + lane];
            float4 we = W4[e*32 + lane];
            float4 g0 = xq4[aidx(a.x)], g1 = xq4[aidx(a.y)];
            float4 g2 = xq4[aidx(a.z)], g3 = xq4[aidx(a.w)];
            MATH4(a.x, g0, bb.x, we.x, x)
            MATH4(a.y, g1, bb.y, we.y, y)
            MATH4(a.z, g2, bb.z, we.z, z)
            MATH4(a.w, g3, bb.w, we.w, w)
        }
    }
    float4 aN0 = mN0, aN1 = mN1, aN2 = mN2, aN3 = mN3;
    float4 aD0 = mD0, aD1 = mD1, aD2 = mD2, aD3 = mD3;
    __syncthreads();   // done reading sensory planes + xq

    // ---- A2: fold recurrent params into SMEM (dense, overwrite) ----
    {
        const float4* s4 = (const float4*)sigma;
        const float4* m4 = (const float4*)mu;
        const float4* w4 = (const float4*)w;
        const float4* e4 = (const float4*)erev;
        const float4* k4 = (const float4*)mask;
        for (int i = tid; i < Un*Un/4; i += NTHR) {
            float4 sg = s4[i], mm = m4[i], ww = w4[i], ee = e4[i], kk = k4[i];
            float4 a, b, we;
            a.x = 0.5f*sg.x; a.y = 0.5f*sg.y; a.z = 0.5f*sg.z; a.w = 0.5f*sg.w;
            b.x = -a.x*mm.x; b.y = -a.y*mm.y; b.z = -a.z*mm.z; b.w = -a.w*mm.w;
            we.x = 0.5f*ww.x*kk.x*ee.x; we.y = 0.5f*ww.y*kk.y*ee.y;
            we.z = 0.5f*ww.z*kk.z*ee.z; we.w = 0.5f*ww.w*kk.w*ee.w;
            ((float4*)sAf)[i] = a; ((float4*)sBf)[i] = b; ((float4*)sWf)[i] = we;
        }
    }
    __syncthreads();

    // ---- scan 2 (tid<128): recurrent col-sums + compaction + base assembly ----
    int cnt = 0;
    if (tid < Un) {
        float n = colSn, d = colSd;
        for (int s = 0; s < Un; ++s) {
            float wv = sWf[s*Un + tid];
            n += wv; d += fabsf(wv);
            if (wv != 0.f) {
                unsigned ai = __float_as_uint(sAf[s*Un + tid]);
                float bv = sBf[s*Un + tid];
                sAf[cnt*Un + tid] = __uint_as_float((ai & 0xFFFFFF80u) | (unsigned)s);
                sBf[cnt*Un + tid] = bv;
                sWf[cnt*Un + tid] = wv;
                cnt++;
            }
        }
        atomicMax(&sL[0], cnt);
        float gl = gleak[tid];
        sNB[tid] = fmaf(gl, vleak[tid], n);
        sDB[tid] = cm[tid]*(float)NUNF + gl + EPSF + d;
    }
    __syncthreads();
    int L = sL[0];
    if (tid < Un) {
        for (int e = cnt; e < L; ++e) {
            sAf[e*Un + tid] = 0.f; sBf[e*Un + tid] = 0.f; sWf[e*Un + tid] = 0.f;
        }
    }
    __syncthreads();

    // ---- init constants; bases folded only into LOW warp's partials ----
    float4 cmt;
    {
        float4 cm4 = *(const float4*)(cm + d0);
        cmt.x = cm4.x*(float)NUNF; cmt.y = cm4.y*(float)NUNF;
        cmt.z = cm4.z*(float)NUNF; cmt.w = cm4.w*(float)NUNF;
        if (!hi) {
            float4 nb4 = *(const float4*)(sNB + d0);
            float4 db4 = *(const float4*)(sDB + d0);
            #define ADD4(T,S) T.x += S.x; T.y += S.y; T.z += S.z; T.w += S.w;
            ADD4(aN0, nb4) ADD4(aN1, nb4) ADD4(aN2, nb4) ADD4(aN3, nb4)
            ADD4(aD0, db4) ADD4(aD1, db4) ADD4(aD2, db4) ADD4(aD3, db4)
            #undef ADD4
        }
    }

    const float4* sA = (const float4*)sAf;
    const float4* sB = (const float4*)sBf;
    const float4* sW = (const float4*)sWf;

    // v init: vqh[s] = half4 (v_b0,v_b1,v_b2,v_b3); LOW writes word0, HIGH word1
    float4 vA, vB;
    {
        int ba = hi ? b2 : b0, bb = hi ? b3 : b1;
        vA = *(const float4*)(state + ba*Un + d0);
        vB = *(const float4*)(state + bb*Un + d0);
        int off = hi ? 1 : 0;
        vqh[2*(d0+0) + off] = packh2(vA.x, vB.x);
        vqh[2*(d0+1) + off] = packh2(vA.y, vB.y);
        vqh[2*(d0+2) + off] = packh2(vA.z, vB.z);
        vqh[2*(d0+3) + off] = packh2(vA.w, vB.w);
    }
    barpair(pid);

    int Lh   = (L + 1) >> 1;
    int eBeg = hi ? Lh : 0;
    int eEnd = hi ? L  : Lh;
    float4* x4 = (float4*)xch;
    const uint2* vq2 = (const uint2*)vqh;

    for (int it = 0; it < NUNF; ++it) {
        mN0 = aN0; mN1 = aN1; mN2 = aN2; mN3 = aN3;
        mD0 = aD0; mD1 = aD1; mD2 = aD2; mD3 = aD3;

        #pragma unroll 2
        for (int e = eBeg; e < eEnd; ++e) {
            float4 a  = sA[e*32 + lane];
            float4 bb = sB[e*32 + lane];
            float4 we = sW[e*32 + lane];
            uint2 gx = vq2[aidx(a.x)], gy = vq2[aidx(a.y)];
            uint2 gz = vq2[aidx(a.z)], gw = vq2[aidx(a.w)];
            float2 vx01 = __half22float2(*(__half2*)&gx.x);
            float2 vx23 = __half22float2(*(__half2*)&gx.y);
            float2 vy01 = __half22float2(*(__half2*)&gy.x);
            float2 vy23 = __half22float2(*(__half2*)&gy.y);
            float2 vz01 = __half22float2(*(__half2*)&gz.x);
            float2 vz23 = __half22float2(*(__half2*)&gz.y);
            float2 vw01 = __half22float2(*(__half2*)&gw.x);
            float2 vw23 = __half22float2(*(__half2*)&gw.y);
            MATHH(a.x, vx01, vx23, bb.x, we.x, x)
            MATHH(a.y, vy01, vy23, bb.y, we.y, y)
            MATHH(a.z, vz01, vz23, bb.z, we.z, z)
            MATHH(a.w, vw01, vw23, bb.w, we.w, w)
        }

        // ---- pairwise exchange & update (fp32) ----
        float4 vnA, vnB;
        if (hi) {
            x4[lane]      = mN0;  x4[32 + lane] = mD0;
            x4[64 + lane] = mN1;  x4[96 + lane] = mD1;
        }
        barpair(pid);
        if (!hi) {
            float4 pn0 = x4[lane],      pd0 = x4[32 + lane];
            float4 pn1 = x4[64 + lane], pd1 = x4[96 + lane];
            vnA.x = __fdividef(fmaf(cmt.x, vA.x, mN0.x + pn0.x), mD0.x + pd0.x);
            vnA.y = __fdividef(fmaf(cmt.y, vA.y, mN0.y + pn0.y), mD0.y + pd0.y);
            vnA.z = __fdividef(fmaf(cmt.z, vA.z, mN0.z + pn0.z), mD0.z + pd0.z);
            vnA.w = __fdividef(fmaf(cmt.w, vA.w, mN0.w + pn0.w), mD0.w + pd0.w);
            vnB.x = __fdividef(fmaf(cmt.x, vB.x, mN1.x + pn1.x), mD1.x + pd1.x);
            vnB.y = __fdividef(fmaf(cmt.y, vB.y, mN1.y + pn1.y), mD1.y + pd1.y);
            vnB.z = __fdividef(fmaf(cmt.z, vB.z, mN1.z + pn1.z), mD1.z + pd1.z);
            vnB.w = __fdividef(fmaf(cmt.w, vB.w, mN1.w + pn1.w), mD1.w + pd1.w);
            x4[lane]      = mN2;  x4[32 + lane] = mD2;
            x4[64 + lane] = mN3;  x4[96 + lane] = mD3;
        }
        barpair(pid);
        if (hi) {
            float4 pn2 = x4[lane],      pd2 = x4[32 + lane];
            float4 pn3 = x4[64 + lane], pd3 = x4[96 + lane];
            vnA.x = __fdividef(fmaf(cmt.x, vA.x, mN2.x + pn2.x), mD2.x + pd2.x);
            vnA.y = __fdividef(fmaf(cmt.y, vA.y, mN2.y + pn2.y), mD2.y + pd2.y);
            vnA.z = __fdividef(fmaf(cmt.z, vA.z, mN2.z + pn2.z), mD2.z + pd2.z);
            vnA.w = __fdividef(fmaf(cmt.w, vA.w, mN2.w + pn2.w), mD2.w + pd2.w);
            vnB.x = __fdividef(fmaf(cmt.x, vB.x, mN3.x + pn3.x), mD3.x + pd3.x);
            vnB.y = __fdividef(fmaf(cmt.y, vB.y, mN3.y + pn3.y), mD3.y + pd3.y);
            vnB.z = __fdividef(fmaf(cmt.z, vB.z, mN3.z + pn3.z), mD3.z + pd3.z);
            vnB.w = __fdividef(fmaf(cmt.w, vB.w, mN3.w + pn3.w), mD3.w + pd3.w);
        }
        {   // publish new v halves as fp16 pairs
            int off = hi ? 1 : 0;
            vqh[2*(d0+0) + off] = packh2(vnA.x, vnB.x);
            vqh[2*(d0+1) + off] = packh2(vnA.y, vnB.y);
            vqh[2*(d0+2) + off] = packh2(vnA.z, vnB.z);
            vqh[2*(d0+3) + off] = packh2(vnA.w, vnB.w);
        }
        vA = vnA; vB = vnB;
        barpair(pid);
    }

    // ---- outputs (full fp32 v) ----
    int ba = hi ? b2 : b0, bb = hi ? b3 : b1;
    ((float4*)(dout + Bn*Mn + ba*Un))[lane] = vA;
    ((float4*)(dout + Bn*Mn + bb*Un))[lane] = vB;
    if (d0 < Mn) {
        float4 ow = *(const float4*)(outw + d0);
        float4 ob = *(const float4*)(outb + d0);
        float4 o;
        o.x = fmaf(vA.x, ow.x, ob.x); o.y = fmaf(vA.y, ow.y, ob.y);
        o.z = fmaf(vA.z, ow.z, ob.z); o.w = fmaf(vA.w, ow.w, ob.w);
        ((float4*)(dout + ba*Mn))[lane] = o;
        o.x = fmaf(vB.x, ow.x, ob.x); o.y = fmaf(vB.y, ow.y, ob.y);
        o.z = fmaf(vB.z, ow.z, ob.z); o.w = fmaf(vB.w, ow.w, ob.w);
        ((float4*)(dout + bb*Mn))[lane] = o;
    }
}

extern "C" void kernel_launch(void* const* d_in, const int* in_sizes, int n_in,
                              void* d_out, int out_size) {
    const float* inputs = (const float*)d_in[0];
    const float* state  = (const float*)d_in[1];
    const float* gleak  = (const float*)d_in[2];
    const float* vleak  = (const float*)d_in[3];
    const float* cm     = (const float*)d_in[4];
    const float* sigma  = (const float*)d_in[5];
    const float* mu     = (const float*)d_in[6];
    const float* w      = (const float*)d_in[7];
    const float* erev   = (const float*)d_in[8];
    const float* ssig   = (const float*)d_in[9];
    const float* smu    = (const float*)d_in[10];
    const float* sw     = (const float*)d_in[11];
    const float* serev  = (const float*)d_in[12];
    const float* mask   = (const float*)d_in[13];
    const float* smask  = (const float*)d_in[14];
    const float* inw    = (const float*)d_in[15];
    const float* inb    = (const float*)d_in[16];
    const float* outw   = (const float*)d_in[17];
    const float* outb   = (const float*)d_in[18];
    float* out = (float*)d_out;

    size_t shmem = (size_t)(3*Un*Un + NPAIR*512*2 + 2*Un + 2) * sizeof(float);  // ~226 KB
    cudaFuncSetAttribute(ltc_all, cudaFuncAttributeMaxDynamicSharedMemorySize, (int)shmem);
    ltc_all<<<148, NTHR, shmem>>>(inputs, state, gleak, vleak, cm,
                                  sigma, mu, w, erev, ssig, smu, sw, serev,
                                  mask, smask, inw, inb, outw, outb, out);
}